// round 15
// baseline (speedup 1.0000x reference)
#include <cuda_runtime.h>
#include <cuda_fp16.h>
#include <math.h>
#include <stdint.h>

// ---------------- problem constants ----------------
constexpr int B_  = 4;
constexpr int T_  = 2048;
constexpr int E_  = 1024;
constexpr int H_  = 16;
constexpr int LQ_ = 2;
constexpr int M_  = B_ * T_;             // 8192
constexpr int NTOT_ = M_ * H_;           // 131072
constexpr size_t PART_ = (size_t)64 * M_;  // one split-K partial plane (fp32)

// ---------------- scratch (device globals; no allocs allowed) ----------------
__device__ __half g_xh[(size_t)M_ * E_];
__device__ __half g_wqT[(size_t)E_ * E_];          // Wq^T (fp16)
__device__ __half g_wkT[(size_t)E_ * E_];          // Wk^T (fp16)
__device__ __half g_gt[(size_t)E_ * E_];           // G~^T = (Wq^T Wk / 32)^T (fp16)
__device__ __half g_yh[(size_t)M_ * E_];           // Y = x G~ (fp16)
__device__ __half g_wvsub[(size_t)64 * E_];        // gathered 64 rows of Wv (fp16)
__device__ __half g_vts[(size_t)64 * M_];          // Vtsub [64][M]
__device__ float  g_zpart[(size_t)M_ * 16];        // per-(row, s-tile) exp partial sums
__device__ float  g_part[4 * PART_];               // Vtsub split-K partials
__device__ float  g_attnT[(size_t)64 * M_];        // attn~^T accumulated via atomics
__device__ __half g_zc192[(size_t)M_ * 192];       // [z_hi | z_lo | z_hi]
__device__ __half g_wo192[(size_t)E_ * 192];       // [W_hi | W_hi | W_lo]
__device__ float  g_base[H_ * 16];

// ---------------- helpers ----------------
__device__ __forceinline__ uint32_t smem_u32(const void* p) {
    uint32_t a;
    asm("{ .reg .u64 t; cvta.to.shared.u64 t, %1; cvt.u32.u64 %0, t; }" : "=r"(a) : "l"(p));
    return a;
}
#define CP16(dst, src) asm volatile("cp.async.cg.shared.global [%0], [%1], 16;" :: "r"(dst), "l"(src))
#define CPCOMMIT()     asm volatile("cp.async.commit_group;")
#define CPWAIT2()      asm volatile("cp.async.wait_group 2;")

__device__ __forceinline__ void ldmx4(uint32_t* r, uint32_t addr) {
    asm volatile("ldmatrix.sync.aligned.m8n8.x4.shared.b16 {%0,%1,%2,%3}, [%4];"
                 : "=r"(r[0]), "=r"(r[1]), "=r"(r[2]), "=r"(r[3]) : "r"(addr));
}
__device__ __forceinline__ void mma16816(float* c, const uint32_t* a, const uint32_t* b) {
    asm volatile(
        "mma.sync.aligned.m16n8k16.row.col.f32.f16.f16.f32 "
        "{%0,%1,%2,%3}, {%4,%5,%6,%7}, {%8,%9}, {%0,%1,%2,%3};"
        : "+f"(c[0]), "+f"(c[1]), "+f"(c[2]), "+f"(c[3])
        : "r"(a[0]), "r"(a[1]), "r"(a[2]), "r"(a[3]), "r"(b[0]), "r"(b[1]));
}
__device__ __forceinline__ uint32_t pack_f16(float lo, float hi) {
    uint32_t u;
    asm("cvt.rn.f16x2.f32 %0, %1, %2;" : "=r"(u) : "f"(hi), "f"(lo));
    return u;
}

// FMA-pipe exp(s - 4): magic-number range reduction + degree-5 2^f poly.
__device__ __forceinline__ float fexp4(float s) {
    float y = fmaf(s, 1.44269504f, -5.77078016f);      // (s-4)*log2(e)
    y = fminf(fmaxf(y, -30.f), 15.f);
    float t = y + 12582912.f;                           // 1.5*2^23 magic
    int   n = __float_as_int(t) - 0x4B400000;
    float f = y - (t - 12582912.f);
    float p =          1.3333558e-3f;
    p = fmaf(p, f, 9.6181291e-3f);
    p = fmaf(p, f, 5.5504109e-2f);
    p = fmaf(p, f, 2.4022651e-1f);
    p = fmaf(p, f, 6.9314718e-1f);
    p = fmaf(p, f, 1.0f);
    return __int_as_float(__float_as_int(p) + (n << 23));
}

// ---------------- fp16 single-pass NT GEMM (mma.sync), BM x 128 tiles, BK=32 ----------------
// C[m,n] = alpha * sum_k A[m,k]*B[n,k]; fp32 acc. K%(32*nsplit)==0.
// EXPM: fused softmax-numerator + attn epilogue. Vt tile is prefetched as the FIRST
// cp.async group into a dedicated smem region (offset VT_OFF), so its latency is
// hidden behind the mainloop and the epilogue needs no cp.async wait.
constexpr int LDSB   = 80;                 // padded row: 32 halves (64B) + 16B pad
constexpr int VT_OFF = 4 * (128 + 128) * LDSB;   // 81920 (after stage area)
constexpr uint32_t SROW = 272;             // 128 halves + 8-half pad (17 x 16B)

template <int BM, bool EXPM>
__global__ __launch_bounds__(256, 2) void gemm_h(
    const __half* __restrict__ Ah, const __half* __restrict__ Bh,
    float* __restrict__ Cf, __half* __restrict__ Ch,
    const __half* __restrict__ Vt, float* __restrict__ Atn,
    int K, int lda, int ldb, int ldc,
    size_t sA, size_t sB, size_t sC, float alpha,
    int nsplit, size_t partStride)
{
    constexpr int APLANE = BM * LDSB;
    constexpr int BPLANE = 128 * LDSB;
    constexpr int STAGE  = APLANE + BPLANE;
    constexpr int NSTG   = 4;
    constexpr int MF     = BM / 32;

    extern __shared__ char smem[];
    const uint32_t sb = smem_u32(smem);
    const int tid = threadIdx.x;
    const int lane = tid & 31;
    const int warp = tid >> 5;
    const int row0 = blockIdx.y * BM;
    const int col0 = blockIdx.x * 128;

    const int zb = blockIdx.z / nsplit;
    const int sp = blockIdx.z - zb * nsplit;
    const int Keff = K / nsplit;

    Ah += zb * sA + (size_t)sp * Keff;
    Bh += zb * sB + (size_t)sp * Keff;
    if (!EXPM) Cf += (size_t)sp * partStride;

    // A loader mapping
    const __half* gA;
    uint32_t aoff;
    if constexpr (BM == 128) {
        const int ar = tid >> 1, ac = (tid & 1) * 2;
        gA = Ah + (size_t)(row0 + ar) * lda + ac * 8;
        aoff = (uint32_t)(ar * LDSB + ac * 16);
    } else {
        const int ar = tid >> 2, ac = tid & 3;
        gA = Ah + (size_t)(row0 + ar) * lda + ac * 8;
        aoff = (uint32_t)(ar * LDSB + ac * 16);
    }
    // B loader mapping (128 rows, 2 chunks/thread)
    const int br = tid >> 1, bc = (tid & 1) * 2;
    const __half* gB = Bh + (size_t)(col0 + br) * ldb + bc * 8;
    const uint32_t boff = (uint32_t)(APLANE + br * LDSB + bc * 16);

    const int ntiles = Keff >> 5;

    auto load_tile = [&](int kt, int slot) {
        const uint32_t base = sb + (uint32_t)slot * STAGE;
        const __half* sa = gA + (size_t)kt * 32;
        const __half* sbp = gB + (size_t)kt * 32;
        if constexpr (BM == 128) {
            CP16(base + aoff,      sa);
            CP16(base + aoff + 16, sa + 8);
        } else {
            CP16(base + aoff, sa);
        }
        CP16(base + boff,      sbp);
        CP16(base + boff + 16, sbp + 8);
    };

    if constexpr (EXPM) {
        // Prefetch Vt slice (64 v x 128 s) as the FIRST cp.async group into VT_OFF.
        const __half* vsrc = Vt + (size_t)(tid >> 2) * M_ + (size_t)zb * T_ + col0 + (tid & 3) * 32;
        const uint32_t vdst = sb + VT_OFF + (uint32_t)((tid >> 2) * SROW + (tid & 3) * 64);
        CP16(vdst,      vsrc);
        CP16(vdst + 16, vsrc + 8);
        CP16(vdst + 32, vsrc + 16);
        CP16(vdst + 48, vsrc + 24);
        CPCOMMIT();
    }

    load_tile(0, 0); CPCOMMIT();
    load_tile(1, 1); CPCOMMIT();
    load_tile(2, 2); CPCOMMIT();

    const int wm = (warp & 1) * (BM / 2);
    const int wn = (warp >> 1) * 32;

    float acc[MF][4][4];
#pragma unroll
    for (int i = 0; i < MF; i++)
#pragma unroll
        for (int j = 0; j < 4; j++)
#pragma unroll
            for (int r = 0; r < 4; r++) acc[i][j][r] = 0.f;

    const uint32_t a_off = (uint32_t)((wm + (lane & 15)) * LDSB + ((lane >> 4) * 8) * 2);
    const int nrow = (lane & 7) + ((lane >> 4) * 8);
    const uint32_t b_off = (uint32_t)(APLANE + (wn + nrow) * LDSB + (((lane >> 3) & 1) * 8) * 2);

    for (int i = 0; i < ntiles; i++) {
        CPWAIT2();
        __syncthreads();
        if (i + 3 < ntiles) load_tile(i + 3, (i + 3) % NSTG);
        CPCOMMIT();

        const uint32_t st = sb + (uint32_t)(i % NSTG) * STAGE;
#pragma unroll
        for (int kk = 0; kk < 2; kk++) {
            uint32_t ah[MF][4], bh[4][2];
#pragma unroll
            for (int im = 0; im < MF; im++)
                ldmx4(ah[im], st + a_off + (uint32_t)(im * 16 * LDSB + kk * 32));
#pragma unroll
            for (int jb = 0; jb < 2; jb++) {
                uint32_t r[4];
                ldmx4(r, st + b_off + (uint32_t)(jb * 16 * LDSB + kk * 32));
                bh[jb * 2][0] = r[0];     bh[jb * 2][1] = r[1];
                bh[jb * 2 + 1][0] = r[2]; bh[jb * 2 + 1][1] = r[3];
            }
#pragma unroll
            for (int im = 0; im < MF; im++)
#pragma unroll
                for (int jn = 0; jn < 4; jn++)
                    mma16816(acc[im][jn], ah[im], bh[jn]);
        }
        __syncthreads();
    }

    if constexpr (EXPM) {
        // ---------- fused exp + rowsum + attnT epilogue (BM == 128) ----------
        const uint32_t s16o  = sb;                      // exp fp16 tile [128 q][SROW]
        const uint32_t vt16o = sb + VT_OFF;             // prefetched Vt tile [64 v][SROW]

        // exp in registers -> fp16 smem tile
        const int er = wm + (lane >> 2);
        const int ec = wn + (lane & 3) * 2;
#pragma unroll
        for (int im = 0; im < 4; im++)
#pragma unroll
            for (int jn = 0; jn < 4; jn++) {
                float e0 = fexp4(acc[im][jn][0]);
                float e1 = fexp4(acc[im][jn][1]);
                float e2 = fexp4(acc[im][jn][2]);
                float e3 = fexp4(acc[im][jn][3]);
                uint32_t adr = s16o + (uint32_t)((er + im * 16) * SROW + (ec + jn * 8) * 2);
                uint32_t p01 = pack_f16(e0, e1);
                uint32_t p23 = pack_f16(e2, e3);
                asm volatile("st.shared.b32 [%0], %1;" :: "r"(adr),            "r"(p01));
                asm volatile("st.shared.b32 [%0], %1;" :: "r"(adr + 8 * SROW), "r"(p23));
            }
        __syncthreads();    // exp tile visible; Vt group completed during mainloop waits

        // row sums -> zpart (Cf)
        {
            const int r2 = tid >> 1;
            const uint32_t rb = s16o + (uint32_t)(r2 * SROW + (tid & 1) * 128);
            float rs = 0.f;
#pragma unroll
            for (int j = 0; j < 8; j++) {
                uint32_t u0, u1, u2, u3;
                asm volatile("ld.shared.v4.b32 {%0,%1,%2,%3}, [%4];"
                             : "=r"(u0), "=r"(u1), "=r"(u2), "=r"(u3) : "r"(rb + j * 16));
                float2 a = __half22float2(*(__half2*)&u0);
                float2 b = __half22float2(*(__half2*)&u1);
                float2 c = __half22float2(*(__half2*)&u2);
                float2 d = __half22float2(*(__half2*)&u3);
                rs += (a.x + a.y) + (b.x + b.y) + (c.x + c.y) + (d.x + d.y);
            }
            rs += __shfl_xor_sync(0xFFFFFFFFu, rs, 1);
            if ((tid & 1) == 0)
                Cf[(size_t)(zb * T_ + row0 + r2) * 16 + blockIdx.x] = rs;
        }

        // attnT: C2[64 v][16 q per warp] = Vt_slice x expTile^T via mma, atomicAdd out
        {
            const int qw = warp * 16;
            const uint32_t a2 = vt16o + (uint32_t)((lane & 15) * SROW + ((lane >> 4) * 8) * 2);
            const int nrow2 = (lane & 7) + ((lane >> 4) * 8);
            const uint32_t b2 = s16o + (uint32_t)((qw + nrow2) * SROW + (((lane >> 3) & 1) * 8) * 2);
            float c2[4][2][4];
#pragma unroll
            for (int i2 = 0; i2 < 4; i2++)
#pragma unroll
                for (int j2 = 0; j2 < 2; j2++)
#pragma unroll
                    for (int r2 = 0; r2 < 4; r2++) c2[i2][j2][r2] = 0.f;
#pragma unroll
            for (int k2 = 0; k2 < 8; k2++) {
                uint32_t bf[4];
                ldmx4(bf, b2 + (uint32_t)(k2 * 32));
#pragma unroll
                for (int im2 = 0; im2 < 4; im2++) {
                    uint32_t af[4];
                    ldmx4(af, a2 + (uint32_t)(im2 * 16 * SROW + k2 * 32));
                    mma16816(c2[im2][0], af, bf);
                    mma16816(c2[im2][1], af, bf + 2);
                }
            }
            const int vb = lane >> 2;
            const int q0 = row0 + qw + (lane & 3) * 2;
            const size_t cb = (size_t)zb * T_;
#pragma unroll
            for (int im2 = 0; im2 < 4; im2++)
#pragma unroll
                for (int jn2 = 0; jn2 < 2; jn2++) {
                    const int v = im2 * 16 + vb;
                    const size_t q = cb + q0 + jn2 * 8;
                    atomicAdd(Atn + (size_t)v * M_ + q,           c2[im2][jn2][0]);
                    atomicAdd(Atn + (size_t)v * M_ + q + 1,       c2[im2][jn2][1]);
                    atomicAdd(Atn + (size_t)(v + 8) * M_ + q,     c2[im2][jn2][2]);
                    atomicAdd(Atn + (size_t)(v + 8) * M_ + q + 1, c2[im2][jn2][3]);
                }
        }
        return;
    }

    // ---- standard epilogue: frags -> smem fp32 -> global ----
    float* se = (float*)smem;                        // [BM][132]
    const int er = wm + (lane >> 2);
    const int ec = wn + (lane & 3) * 2;
#pragma unroll
    for (int im = 0; im < MF; im++)
#pragma unroll
        for (int jn = 0; jn < 4; jn++) {
            float* p0 = se + (size_t)(er + im * 16) * 132 + ec + jn * 8;
            p0[0] = acc[im][jn][0];
            p0[1] = acc[im][jn][1];
            p0[132 * 8]     = acc[im][jn][2];
            p0[132 * 8 + 1] = acc[im][jn][3];
        }
    __syncthreads();
    {
        constexpr int TPR = 256 / BM;
        constexpr int CW  = 128 / TPR;
        const int row = tid / TPR;
        const int hc  = (tid % TPR) * CW;
        const size_t crow = (size_t)zb * sC + (size_t)(row0 + row) * ldc + col0 + hc;
#pragma unroll
        for (int j = 0; j < CW / 4; j++) {
            float4 v = *(const float4*)(se + (size_t)row * 132 + hc + j * 4);
            v.x *= alpha; v.y *= alpha; v.z *= alpha; v.w *= alpha;
            if (Cf) *(float4*)(Cf + crow + j * 4) = v;
            if (Ch) {
                uint2 u = make_uint2(pack_f16(v.x, v.y), pack_f16(v.z, v.w));
                *(uint2*)(Ch + crow + j * 4) = u;
            }
        }
    }
}

constexpr int SMEM_DYN_128 = 4 * (128 + 128) * LDSB;   // 81920
constexpr int SMEM_DYN_64  = 4 * (64 + 128) * LDSB;    // 61440
constexpr int SMEM_DYN_EXP = VT_OFF + 64 * (int)SROW;  // 81920 + 17408 = 99328

// ---------------- quantum circuit device pieces ----------------
template <int BIT>
__device__ __forceinline__ void apply_ry_bit(float st[16], float half_theta)
{
    float s, c;
    sincosf(half_theta, &s, &c);
#pragma unroll
    for (int i = 0; i < 16; i++) {
        if (!(i & BIT)) {
            float a0 = st[i], a1 = st[i | BIT];
            st[i]       = c * a0 - s * a1;
            st[i | BIT] = s * a0 + c * a1;
        }
    }
}
template <int BC, int BT>
__device__ __forceinline__ void apply_cnot(float st[16])
{
#pragma unroll
    for (int i = 0; i < 16; i++) {
        if ((i & BC) && !(i & BT)) {
            float tmp = st[i]; st[i] = st[i | BT]; st[i | BT] = tmp;
        }
    }
}

// ---------------- fused prep: conv x, transpose Wq/Wk, wvsub, wosub, base, zero attnT ----------------
__global__ __launch_bounds__(256) void prep_kernel(
    const float* __restrict__ x,  const float* __restrict__ Wq,
    const float* __restrict__ Wk, const float* __restrict__ Wv,
    const float* __restrict__ Wo, const float* __restrict__ qp,
    __half* __restrict__ xh, __half* __restrict__ wqT, __half* __restrict__ wkT,
    __half* __restrict__ wvs, __half* __restrict__ wo192, float* __restrict__ base,
    float* __restrict__ atn)
{
    __shared__ float ts[64][65];
    const int b = blockIdx.x;
    const int tid = threadIdx.x;

    if (b < 8192) {
        size_t i = ((size_t)b * 256 + tid) * 4;
        float4 v = *(const float4*)(x + i);
        *(uint2*)(xh + i) = make_uint2(pack_f16(v.x, v.y), pack_f16(v.z, v.w));
    } else if (b < 8704) {
        const bool isQ = b < 8448;
        const int tile = b - (isQ ? 8192 : 8448);
        const float* W = isQ ? Wq : Wk;
        __half* WT = isQ ? wqT : wkT;
        const int tr = (tile >> 4) * 64;
        const int tc = (tile & 15) * 64;
        const int lr = tid >> 2;
        const int lc = (tid & 3) * 16;
#pragma unroll
        for (int j = 0; j < 16; j += 4) {
            float4 v = *(const float4*)(W + (size_t)(tr + lr) * E_ + tc + lc + j);
            ts[lr][lc + j + 0] = v.x; ts[lr][lc + j + 1] = v.y;
            ts[lr][lc + j + 2] = v.z; ts[lr][lc + j + 3] = v.w;
        }
        __syncthreads();
#pragma unroll
        for (int j = 0; j < 16; j += 4) {
            uint2 u = make_uint2(
                pack_f16(ts[lc + j + 0][lr], ts[lc + j + 1][lr]),
                pack_f16(ts[lc + j + 2][lr], ts[lc + j + 3][lr]));
            *(uint2*)(WT + (size_t)(tc + lr) * E_ + tr + lc + j) = u;
        }
    } else if (b < 8768) {
        int idx = (b - 8704) * 256 + tid;
        int j = idx >> 8;
        int c = (idx & 255) * 4;
        const float* src = Wv + (size_t)((j >> 2) * 64 + (j & 3)) * E_ + c;
        float4 v = *(const float4*)src;
        *(uint2*)(wvs + (size_t)j * E_ + c) = make_uint2(pack_f16(v.x, v.y), pack_f16(v.z, v.w));
    } else if (b < 9024) {
        int idx = (b - 8768) * 256 + tid;
        int e = idx >> 6, j = idx & 63;
        float v = Wo[(size_t)e * E_ + ((j >> 2) << 6) + (j & 3)];
        __half h = __float2half(v);
        __half l = __float2half(v - __half2float(h));
        size_t o = (size_t)e * 192 + j;
        wo192[o]       = h;
        wo192[o + 64]  = h;
        wo192[o + 128] = l;
    } else if (b < 9536) {
        // zero attnT: 64*8192 floats = 512 blocks x 256 thr x float4
        size_t i = ((size_t)(b - 9024) * 256 + tid) * 4;
        *(float4*)(atn + i) = make_float4(0.f, 0.f, 0.f, 0.f);
    } else if (tid < H_) {
        float st[16];
#pragma unroll
        for (int i = 0; i < 16; i++) st[i] = 0.f;
        st[0] = 1.f;
#pragma unroll
        for (int l = 0; l < LQ_; l++) {
            const float* p = qp + (tid * LQ_ + l) * 4;
            apply_ry_bit<8>(st, 0.5f * p[0]);
            apply_ry_bit<4>(st, 0.5f * p[1]);
            apply_ry_bit<2>(st, 0.5f * p[2]);
            apply_ry_bit<1>(st, 0.5f * p[3]);
            apply_cnot<8, 4>(st);
            apply_cnot<4, 2>(st);
            apply_cnot<2, 1>(st);
            apply_cnot<1, 8>(st);
        }
#pragma unroll
        for (int i = 0; i < 16; i++) base[tid * 16 + i] = st[i];
    }
}

// ---------------- reduce Vtsub split-K partials -> fp16 ----------------
__global__ __launch_bounds__(256) void vred_kernel(const float* __restrict__ p, __half* __restrict__ vts)
{
    size_t i = ((size_t)blockIdx.x * 256 + threadIdx.x) * 4;
    float4 a = *(const float4*)(p + i);
    float4 b = *(const float4*)(p + i + PART_);
    float4 c = *(const float4*)(p + i + 2 * PART_);
    float4 d = *(const float4*)(p + i + 3 * PART_);
    a.x += b.x + c.x + d.x;
    a.y += b.y + c.y + d.y;
    a.z += b.z + c.z + d.z;
    a.w += b.w + c.w + d.w;
    *(uint2*)(vts + i) = make_uint2(pack_f16(a.x, a.y), pack_f16(a.z, a.w));
}

// ---------------- quantum: Z from 16 zpart partials, normalize attnT, circuit ----------------
__global__ __launch_bounds__(256) void quantum_kernel(
    const float* __restrict__ atn, const float* __restrict__ zp,
    const float* __restrict__ base, __half* __restrict__ zc192)
{
    int idx = blockIdx.x * 256 + threadIdx.x;
    if (idx >= NTOT_) return;
    int h  = idx >> 13;
    int bt = idx & (M_ - 1);

    const float4* zpp = (const float4*)(zp + (size_t)bt * 16);
    float4 a = zpp[0], b = zpp[1], c = zpp[2], d = zpp[3];
    float Z = (((a.x + a.y) + (a.z + a.w)) + ((b.x + b.y) + (b.z + b.w)))
            + (((c.x + c.y) + (c.z + c.w)) + ((d.x + d.y) + (d.z + d.w)));
    const float rz = 0.5f / Z;

    float ang[4];
#pragma unroll
    for (int q = 0; q < 4; q++)
        ang[q] = atn[(size_t)(h * 4 + q) * M_ + bt] * rz;

    float st[16];
#pragma unroll
    for (int i = 0; i < 16; i++) st[i] = base[h * 16 + i];

    apply_ry_bit<8>(st, ang[0]);
    apply_ry_bit<4>(st, ang[1]);
    apply_ry_bit<2>(st, ang[2]);
    apply_ry_bit<1>(st, ang[3]);

    float z[4] = {0.f, 0.f, 0.f, 0.f};
#pragma unroll
    for (int i = 0; i < 16; i++) {
        float p = st[i] * st[i];
        z[0] += (i & 8) ? -p : p;
        z[1] += (i & 4) ? -p : p;
        z[2] += (i & 2) ? -p : p;
        z[3] += (i & 1) ? -p : p;
    }

    __half hq[4], lq[4];
#pragma unroll
    for (int q = 0; q < 4; q++) {
        hq[q] = __float2half(z[q]);
        lq[q] = __float2half(z[q] - __half2float(hq[q]));
    }
    __half2 h01 = __halves2half2(hq[0], hq[1]);
    __half2 h23 = __halves2half2(hq[2], hq[3]);
    __half2 l01 = __halves2half2(lq[0], lq[1]);
    __half2 l23 = __halves2half2(lq[2], lq[3]);

    size_t o = (size_t)bt * 192 + h * 4;
    *(__half2*)(zc192 + o)       = h01;
    *(__half2*)(zc192 + o + 2)   = h23;
    *(__half2*)(zc192 + o + 64)  = l01;
    *(__half2*)(zc192 + o + 66)  = l23;
    *(__half2*)(zc192 + o + 128) = h01;
    *(__half2*)(zc192 + o + 130) = h23;
}

// ---------------- launch ----------------
extern "C" void kernel_launch(void* const* d_in, const int* in_sizes, int n_in,
                              void* d_out, int out_size)
{
    (void)in_sizes; (void)n_in; (void)out_size;
    const float* x  = (const float*)d_in[0];
    const float* Wq = (const float*)d_in[1];
    const float* Wk = (const float*)d_in[2];
    const float* Wv = (const float*)d_in[3];
    const float* Wo = (const float*)d_in[4];
    const float* qp = (const float*)d_in[5];
    float* out = (float*)d_out;

    __half *xh, *wqT, *wkT, *gt, *yh, *wvs, *vts, *zc192, *wo192;
    float *zp, *part, *atn, *pb;
    cudaGetSymbolAddress((void**)&xh,    g_xh);
    cudaGetSymbolAddress((void**)&wqT,   g_wqT);
    cudaGetSymbolAddress((void**)&wkT,   g_wkT);
    cudaGetSymbolAddress((void**)&gt,    g_gt);
    cudaGetSymbolAddress((void**)&yh,    g_yh);
    cudaGetSymbolAddress((void**)&wvs,   g_wvsub);
    cudaGetSymbolAddress((void**)&vts,   g_vts);
    cudaGetSymbolAddress((void**)&zp,    g_zpart);
    cudaGetSymbolAddress((void**)&part,  g_part);
    cudaGetSymbolAddress((void**)&atn,   g_attnT);
    cudaGetSymbolAddress((void**)&zc192, g_zc192);
    cudaGetSymbolAddress((void**)&wo192, g_wo192);
    cudaGetSymbolAddress((void**)&pb,    g_base);

    cudaFuncSetAttribute((const void*)gemm_h<128, false>, cudaFuncAttributeMaxDynamicSharedMemorySize, SMEM_DYN_128);
    cudaFuncSetAttribute((const void*)gemm_h<128, true>,  cudaFuncAttributeMaxDynamicSharedMemorySize, SMEM_DYN_EXP);
    cudaFuncSetAttribute((const void*)gemm_h<64, false>,  cudaFuncAttributeMaxDynamicSharedMemorySize, SMEM_DYN_64);

    // fused prep (includes attnT zeroing)
    prep_kernel<<<9537, 256>>>(x, Wq, Wk, Wv, Wo, qp, xh, wqT, wkT, wvs, wo192, pb, atn);

    // Gt = (Wq^T Wk / 32)^T (fp16 out)
    {
        dim3 g(E_ / 128, E_ / 64);
        gemm_h<64, false><<<g, 256, SMEM_DYN_64>>>(wkT, wqT, nullptr, gt, nullptr, nullptr,
                                                   E_, E_, E_, E_, 0, 0, 0, 1.f / 32.f, 1, 0);
    }
    // Vtsub = Wvsub @ x^T : split-K 4 -> fp32 partials
    {
        dim3 g(M_ / 128, 1, 4);
        gemm_h<64, false><<<g, 256, SMEM_DYN_64>>>(wvs, xh, part, nullptr, nullptr, nullptr,
                                                   E_, E_, E_, M_, 0, 0, 0, 1.f, 4, PART_);
    }
    vred_kernel<<<(int)(PART_ / 1024), 256>>>(part, vts);
    // Y = x @ G~ (fp16 out)
    {
        dim3 g(E_ / 128, M_ / 128);
        gemm_h<128, false><<<g, 256, SMEM_DYN_128>>>(xh, gt, nullptr, yh, nullptr, nullptr,
                                                     E_, E_, E_, E_, 0, 0, 0, 1.f, 1, 0);
    }
    // scores: exp(Y x^T - 4) fused with rowsums (zpart) and attnT accumulation (atomic)
    {
        dim3 g(T_ / 128, T_ / 128, B_);
        gemm_h<128, true><<<g, 256, SMEM_DYN_EXP>>>(yh, xh, zp, nullptr, vts, atn,
                                                    E_, E_, E_, T_,
                                                    (size_t)T_ * E_, (size_t)T_ * E_, (size_t)T_ * T_,
                                                    1.f, 1, 0);
    }
    quantum_kernel<<<NTOT_ / 256, 256>>>(atn, zp, pb, zc192);
    // out = zc @ WoSub^T via plane-concat K=192 fp16 GEMM
    {
        dim3 g(E_ / 128, M_ / 128);
        gemm_h<128, false><<<g, 256, SMEM_DYN_128>>>(zc192, wo192, out, nullptr, nullptr, nullptr,
                                                     192, 192, 192, E_, 0, 0, 0, 1.f, 1, 0);
    }
}

// round 16
// speedup vs baseline: 1.0066x; 1.0066x over previous
#include <cuda_runtime.h>
#include <cuda_fp16.h>
#include <math.h>
#include <stdint.h>

// ---------------- problem constants ----------------
constexpr int B_  = 4;
constexpr int T_  = 2048;
constexpr int E_  = 1024;
constexpr int H_  = 16;
constexpr int LQ_ = 2;
constexpr int M_  = B_ * T_;             // 8192
constexpr int NTOT_ = M_ * H_;           // 131072

// ---------------- scratch (device globals; no allocs allowed) ----------------
__device__ __half g_xh[(size_t)M_ * E_];
__device__ __half g_wqT[(size_t)E_ * E_];          // Wq^T (fp16)
__device__ __half g_wkT[(size_t)E_ * E_];          // Wk^T (fp16)
__device__ __half g_gt[(size_t)E_ * E_];           // G~^T = (Wq^T Wk / 32)^T (fp16)
__device__ __half g_yh[(size_t)M_ * E_];           // Y = x G~ (fp16)
__device__ __half g_wvsub[(size_t)64 * E_];        // gathered 64 rows of Wv (fp16)
__device__ __half g_vts[(size_t)64 * M_];          // Vtsub [64][M] (fp16)
__device__ float  g_zpart[(size_t)M_ * 16];        // per-(row, s-tile) exp partial sums
__device__ float  g_attnT[(size_t)64 * M_];        // attn~^T accumulated via atomics
__device__ __half g_zc192[(size_t)M_ * 192];       // [z_hi | z_lo | z_hi]
__device__ __half g_wo192[(size_t)E_ * 192];       // [W_hi | W_hi | W_lo]
__device__ float  g_base[H_ * 16];

// ---------------- helpers ----------------
__device__ __forceinline__ uint32_t smem_u32(const void* p) {
    uint32_t a;
    asm("{ .reg .u64 t; cvta.to.shared.u64 t, %1; cvt.u32.u64 %0, t; }" : "=r"(a) : "l"(p));
    return a;
}
#define CP16(dst, src) asm volatile("cp.async.cg.shared.global [%0], [%1], 16;" :: "r"(dst), "l"(src))
#define CPCOMMIT()     asm volatile("cp.async.commit_group;")
#define CPWAIT2()      asm volatile("cp.async.wait_group 2;")
#define CPWAIT0()      asm volatile("cp.async.wait_group 0;")

__device__ __forceinline__ void ldmx4(uint32_t* r, uint32_t addr) {
    asm volatile("ldmatrix.sync.aligned.m8n8.x4.shared.b16 {%0,%1,%2,%3}, [%4];"
                 : "=r"(r[0]), "=r"(r[1]), "=r"(r[2]), "=r"(r[3]) : "r"(addr));
}
__device__ __forceinline__ void mma16816(float* c, const uint32_t* a, const uint32_t* b) {
    asm volatile(
        "mma.sync.aligned.m16n8k16.row.col.f32.f16.f16.f32 "
        "{%0,%1,%2,%3}, {%4,%5,%6,%7}, {%8,%9}, {%0,%1,%2,%3};"
        : "+f"(c[0]), "+f"(c[1]), "+f"(c[2]), "+f"(c[3])
        : "r"(a[0]), "r"(a[1]), "r"(a[2]), "r"(a[3]), "r"(b[0]), "r"(b[1]));
}
__device__ __forceinline__ uint32_t pack_f16(float lo, float hi) {
    uint32_t u;
    asm("cvt.rn.f16x2.f32 %0, %1, %2;" : "=r"(u) : "f"(hi), "f"(lo));
    return u;
}

// FMA-pipe exp(s - 4): magic-number range reduction + degree-5 2^f poly.
__device__ __forceinline__ float fexp4(float s) {
    float y = fmaf(s, 1.44269504f, -5.77078016f);      // (s-4)*log2(e)
    y = fminf(fmaxf(y, -30.f), 15.f);
    float t = y + 12582912.f;                           // 1.5*2^23 magic
    int   n = __float_as_int(t) - 0x4B400000;
    float f = y - (t - 12582912.f);
    float p =          1.3333558e-3f;
    p = fmaf(p, f, 9.6181291e-3f);
    p = fmaf(p, f, 5.5504109e-2f);
    p = fmaf(p, f, 2.4022651e-1f);
    p = fmaf(p, f, 6.9314718e-1f);
    p = fmaf(p, f, 1.0f);
    return __int_as_float(__float_as_int(p) + (n << 23));
}

// ---------------- fp16 single-pass NT GEMM (mma.sync), BM x 128 tiles, BK=32 ----------------
// C[m,n] = alpha * sum_k A[m,k]*B[n,k]; fp32 acc. K%32==0.
// EXPM: fused softmax-numerator + attn epilogue:
//   exp(acc-4) -> fp16 smem tile; row sums -> Cf (zpart, indexed by blockIdx.x);
//   Vt slice (cp.async) x expTile via mma -> atomicAdd into Atn. No expS to global.
constexpr int LDSB  = 80;                  // padded row: 32 halves (64B) + 16B pad

template <int BM, bool EXPM>
__global__ __launch_bounds__(256, 2) void gemm_h(
    const __half* __restrict__ Ah, const __half* __restrict__ Bh,
    float* __restrict__ Cf, __half* __restrict__ Ch,
    const __half* __restrict__ Vt, float* __restrict__ Atn,
    int K, int lda, int ldb, int ldc,
    size_t sA, size_t sB, size_t sC, float alpha)
{
    constexpr int APLANE = BM * LDSB;
    constexpr int BPLANE = 128 * LDSB;
    constexpr int STAGE  = APLANE + BPLANE;
    constexpr int NSTG   = 4;
    constexpr int MF     = BM / 32;

    extern __shared__ char smem[];
    const uint32_t sb = smem_u32(smem);
    const int tid = threadIdx.x;
    const int lane = tid & 31;
    const int warp = tid >> 5;
    const int row0 = blockIdx.y * BM;
    const int col0 = blockIdx.x * 128;
    const int zb = blockIdx.z;

    Ah += zb * sA;
    Bh += zb * sB;

    // A loader mapping
    const __half* gA;
    uint32_t aoff;
    if constexpr (BM == 128) {
        const int ar = tid >> 1, ac = (tid & 1) * 2;
        gA = Ah + (size_t)(row0 + ar) * lda + ac * 8;
        aoff = (uint32_t)(ar * LDSB + ac * 16);
    } else {
        const int ar = tid >> 2, ac = tid & 3;
        gA = Ah + (size_t)(row0 + ar) * lda + ac * 8;
        aoff = (uint32_t)(ar * LDSB + ac * 16);
    }
    // B loader mapping (128 rows, 2 chunks/thread)
    const int br = tid >> 1, bc = (tid & 1) * 2;
    const __half* gB = Bh + (size_t)(col0 + br) * ldb + bc * 8;
    const uint32_t boff = (uint32_t)(APLANE + br * LDSB + bc * 16);

    const int ntiles = K >> 5;

    auto load_tile = [&](int kt, int slot) {
        const uint32_t base = sb + (uint32_t)slot * STAGE;
        const __half* sa = gA + (size_t)kt * 32;
        const __half* sbp = gB + (size_t)kt * 32;
        if constexpr (BM == 128) {
            CP16(base + aoff,      sa);
            CP16(base + aoff + 16, sa + 8);
        } else {
            CP16(base + aoff, sa);
        }
        CP16(base + boff,      sbp);
        CP16(base + boff + 16, sbp + 8);
    };

    load_tile(0, 0); CPCOMMIT();
    load_tile(1, 1); CPCOMMIT();
    load_tile(2, 2); CPCOMMIT();

    const int wm = (warp & 1) * (BM / 2);
    const int wn = (warp >> 1) * 32;

    float acc[MF][4][4];
#pragma unroll
    for (int i = 0; i < MF; i++)
#pragma unroll
        for (int j = 0; j < 4; j++)
#pragma unroll
            for (int r = 0; r < 4; r++) acc[i][j][r] = 0.f;

    const uint32_t a_off = (uint32_t)((wm + (lane & 15)) * LDSB + ((lane >> 4) * 8) * 2);
    const int nrow = (lane & 7) + ((lane >> 4) * 8);
    const uint32_t b_off = (uint32_t)(APLANE + (wn + nrow) * LDSB + (((lane >> 3) & 1) * 8) * 2);

    for (int i = 0; i < ntiles; i++) {
        CPWAIT2();
        __syncthreads();
        if (i + 3 < ntiles) load_tile(i + 3, (i + 3) % NSTG);
        CPCOMMIT();

        const uint32_t st = sb + (uint32_t)(i % NSTG) * STAGE;
#pragma unroll
        for (int kk = 0; kk < 2; kk++) {
            uint32_t ah[MF][4], bh[4][2];
#pragma unroll
            for (int im = 0; im < MF; im++)
                ldmx4(ah[im], st + a_off + (uint32_t)(im * 16 * LDSB + kk * 32));
#pragma unroll
            for (int jb = 0; jb < 2; jb++) {
                uint32_t r[4];
                ldmx4(r, st + b_off + (uint32_t)(jb * 16 * LDSB + kk * 32));
                bh[jb * 2][0] = r[0];     bh[jb * 2][1] = r[1];
                bh[jb * 2 + 1][0] = r[2]; bh[jb * 2 + 1][1] = r[3];
            }
#pragma unroll
            for (int im = 0; im < MF; im++)
#pragma unroll
                for (int jn = 0; jn < 4; jn++)
                    mma16816(acc[im][jn], ah[im], bh[jn]);
        }
        __syncthreads();
    }

    if constexpr (EXPM) {
        // ---------- fused exp + rowsum + attnT epilogue (BM == 128) ----------
        constexpr uint32_t SROW = 272;                  // 128 halves + 8-half pad (17x16B)
        const uint32_t s16o  = sb;                      // exp fp16 tile [128 q][SROW]
        const uint32_t vt16o = sb + 128u * SROW;        // Vt fp16 tile [64 v][SROW]

        // issue Vt slice load: rows v=0..63, cols s = zb*T_ + col0 .. +128
        {
            const __half* vsrc = Vt + (size_t)(tid >> 2) * M_ + (size_t)zb * T_ + col0 + (tid & 3) * 32;
            const uint32_t vdst = vt16o + (uint32_t)((tid >> 2) * SROW + (tid & 3) * 64);
            CP16(vdst,      vsrc);
            CP16(vdst + 16, vsrc + 8);
            CP16(vdst + 32, vsrc + 16);
            CP16(vdst + 48, vsrc + 24);
            CPCOMMIT();
        }
        // exp in registers -> fp16 smem tile
        const int er = wm + (lane >> 2);
        const int ec = wn + (lane & 3) * 2;
#pragma unroll
        for (int im = 0; im < 4; im++)
#pragma unroll
            for (int jn = 0; jn < 4; jn++) {
                float e0 = fexp4(acc[im][jn][0]);
                float e1 = fexp4(acc[im][jn][1]);
                float e2 = fexp4(acc[im][jn][2]);
                float e3 = fexp4(acc[im][jn][3]);
                uint32_t adr = s16o + (uint32_t)((er + im * 16) * SROW + (ec + jn * 8) * 2);
                uint32_t p01 = pack_f16(e0, e1);
                uint32_t p23 = pack_f16(e2, e3);
                asm volatile("st.shared.b32 [%0], %1;" :: "r"(adr),            "r"(p01));
                asm volatile("st.shared.b32 [%0], %1;" :: "r"(adr + 8 * SROW), "r"(p23));
            }
        CPWAIT0();
        __syncthreads();

        // row sums -> zpart (Cf)
        {
            const int r2 = tid >> 1;
            const uint32_t rb = s16o + (uint32_t)(r2 * SROW + (tid & 1) * 128);
            float rs = 0.f;
#pragma unroll
            for (int j = 0; j < 8; j++) {
                uint32_t u0, u1, u2, u3;
                asm volatile("ld.shared.v4.b32 {%0,%1,%2,%3}, [%4];"
                             : "=r"(u0), "=r"(u1), "=r"(u2), "=r"(u3) : "r"(rb + j * 16));
                float2 a = __half22float2(*(__half2*)&u0);
                float2 b = __half22float2(*(__half2*)&u1);
                float2 c = __half22float2(*(__half2*)&u2);
                float2 d = __half22float2(*(__half2*)&u3);
                rs += (a.x + a.y) + (b.x + b.y) + (c.x + c.y) + (d.x + d.y);
            }
            rs += __shfl_xor_sync(0xFFFFFFFFu, rs, 1);
            if ((tid & 1) == 0)
                Cf[(size_t)(zb * T_ + row0 + r2) * 16 + blockIdx.x] = rs;
        }

        // attnT: C2[64 v][16 q per warp] = Vt_slice x expTile^T via mma, atomicAdd out
        {
            const int qw = warp * 16;
            const uint32_t a2 = vt16o + (uint32_t)((lane & 15) * SROW + ((lane >> 4) * 8) * 2);
            const int nrow2 = (lane & 7) + ((lane >> 4) * 8);
            const uint32_t b2 = s16o + (uint32_t)((qw + nrow2) * SROW + (((lane >> 3) & 1) * 8) * 2);
            float c2[4][2][4];
#pragma unroll
            for (int i2 = 0; i2 < 4; i2++)
#pragma unroll
                for (int j2 = 0; j2 < 2; j2++)
#pragma unroll
                    for (int r2 = 0; r2 < 4; r2++) c2[i2][j2][r2] = 0.f;
#pragma unroll
            for (int k2 = 0; k2 < 8; k2++) {
                uint32_t bf[4];
                ldmx4(bf, b2 + (uint32_t)(k2 * 32));
#pragma unroll
                for (int im2 = 0; im2 < 4; im2++) {
                    uint32_t af[4];
                    ldmx4(af, a2 + (uint32_t)(im2 * 16 * SROW + k2 * 32));
                    mma16816(c2[im2][0], af, bf);
                    mma16816(c2[im2][1], af, bf + 2);
                }
            }
            const int vb = lane >> 2;
            const int q0 = row0 + qw + (lane & 3) * 2;
            const size_t cb = (size_t)zb * T_;
#pragma unroll
            for (int im2 = 0; im2 < 4; im2++)
#pragma unroll
                for (int jn2 = 0; jn2 < 2; jn2++) {
                    const int v = im2 * 16 + vb;
                    const size_t q = cb + q0 + jn2 * 8;
                    atomicAdd(Atn + (size_t)v * M_ + q,           c2[im2][jn2][0]);
                    atomicAdd(Atn + (size_t)v * M_ + q + 1,       c2[im2][jn2][1]);
                    atomicAdd(Atn + (size_t)(v + 8) * M_ + q,     c2[im2][jn2][2]);
                    atomicAdd(Atn + (size_t)(v + 8) * M_ + q + 1, c2[im2][jn2][3]);
                }
        }
        return;
    }

    // ---- standard epilogue: frags -> smem fp32 -> global ----
    float* se = (float*)smem;                        // [BM][132]
    const int er = wm + (lane >> 2);
    const int ec = wn + (lane & 3) * 2;
#pragma unroll
    for (int im = 0; im < MF; im++)
#pragma unroll
        for (int jn = 0; jn < 4; jn++) {
            float* p0 = se + (size_t)(er + im * 16) * 132 + ec + jn * 8;
            p0[0] = acc[im][jn][0];
            p0[1] = acc[im][jn][1];
            p0[132 * 8]     = acc[im][jn][2];
            p0[132 * 8 + 1] = acc[im][jn][3];
        }
    __syncthreads();
    {
        constexpr int TPR = 256 / BM;
        constexpr int CW  = 128 / TPR;
        const int row = tid / TPR;
        const int hc  = (tid % TPR) * CW;
        const size_t crow = (size_t)zb * sC + (size_t)(row0 + row) * ldc + col0 + hc;
#pragma unroll
        for (int j = 0; j < CW / 4; j++) {
            float4 v = *(const float4*)(se + (size_t)row * 132 + hc + j * 4);
            v.x *= alpha; v.y *= alpha; v.z *= alpha; v.w *= alpha;
            if (Cf) *(float4*)(Cf + crow + j * 4) = v;
            if (Ch) {
                uint2 u = make_uint2(pack_f16(v.x, v.y), pack_f16(v.z, v.w));
                *(uint2*)(Ch + crow + j * 4) = u;
            }
        }
    }
}

constexpr int SMEM_DYN_128 = 4 * (128 + 128) * LDSB;   // 81920
constexpr int SMEM_DYN_64  = 4 * (64 + 128) * LDSB;    // 61440

// ---------------- quantum circuit device pieces ----------------
template <int BIT>
__device__ __forceinline__ void apply_ry_bit(float st[16], float half_theta)
{
    float s, c;
    sincosf(half_theta, &s, &c);
#pragma unroll
    for (int i = 0; i < 16; i++) {
        if (!(i & BIT)) {
            float a0 = st[i], a1 = st[i | BIT];
            st[i]       = c * a0 - s * a1;
            st[i | BIT] = s * a0 + c * a1;
        }
    }
}
template <int BC, int BT>
__device__ __forceinline__ void apply_cnot(float st[16])
{
#pragma unroll
    for (int i = 0; i < 16; i++) {
        if ((i & BC) && !(i & BT)) {
            float tmp = st[i]; st[i] = st[i | BT]; st[i | BT] = tmp;
        }
    }
}

// ---------------- fused prep: conv x, transpose Wq/Wk, wvsub, wosub, base ----------------
__global__ __launch_bounds__(256) void prep_kernel(
    const float* __restrict__ x,  const float* __restrict__ Wq,
    const float* __restrict__ Wk, const float* __restrict__ Wv,
    const float* __restrict__ Wo, const float* __restrict__ qp,
    __half* __restrict__ xh, __half* __restrict__ wqT, __half* __restrict__ wkT,
    __half* __restrict__ wvs, __half* __restrict__ wo192, float* __restrict__ base)
{
    __shared__ float ts[64][65];
    const int b = blockIdx.x;
    const int tid = threadIdx.x;

    if (b < 8192) {
        size_t i = ((size_t)b * 256 + tid) * 4;
        float4 v = *(const float4*)(x + i);
        *(uint2*)(xh + i) = make_uint2(pack_f16(v.x, v.y), pack_f16(v.z, v.w));
    } else if (b < 8704) {
        const bool isQ = b < 8448;
        const int tile = b - (isQ ? 8192 : 8448);
        const float* W = isQ ? Wq : Wk;
        __half* WT = isQ ? wqT : wkT;
        const int tr = (tile >> 4) * 64;
        const int tc = (tile & 15) * 64;
        const int lr = tid >> 2;
        const int lc = (tid & 3) * 16;
#pragma unroll
        for (int j = 0; j < 16; j += 4) {
            float4 v = *(const float4*)(W + (size_t)(tr + lr) * E_ + tc + lc + j);
            ts[lr][lc + j + 0] = v.x; ts[lr][lc + j + 1] = v.y;
            ts[lr][lc + j + 2] = v.z; ts[lr][lc + j + 3] = v.w;
        }
        __syncthreads();
#pragma unroll
        for (int j = 0; j < 16; j += 4) {
            uint2 u = make_uint2(
                pack_f16(ts[lc + j + 0][lr], ts[lc + j + 1][lr]),
                pack_f16(ts[lc + j + 2][lr], ts[lc + j + 3][lr]));
            *(uint2*)(WT + (size_t)(tc + lr) * E_ + tr + lc + j) = u;
        }
    } else if (b < 8768) {
        int idx = (b - 8704) * 256 + tid;
        int j = idx >> 8;
        int c = (idx & 255) * 4;
        const float* src = Wv + (size_t)((j >> 2) * 64 + (j & 3)) * E_ + c;
        float4 v = *(const float4*)src;
        *(uint2*)(wvs + (size_t)j * E_ + c) = make_uint2(pack_f16(v.x, v.y), pack_f16(v.z, v.w));
    } else if (b < 9024) {
        int idx = (b - 8768) * 256 + tid;
        int e = idx >> 6, j = idx & 63;
        float v = Wo[(size_t)e * E_ + ((j >> 2) << 6) + (j & 3)];
        __half h = __float2half(v);
        __half l = __float2half(v - __half2float(h));
        size_t o = (size_t)e * 192 + j;
        wo192[o]       = h;
        wo192[o + 64]  = h;
        wo192[o + 128] = l;
    } else if (tid < H_) {
        float st[16];
#pragma unroll
        for (int i = 0; i < 16; i++) st[i] = 0.f;
        st[0] = 1.f;
#pragma unroll
        for (int l = 0; l < LQ_; l++) {
            const float* p = qp + (tid * LQ_ + l) * 4;
            apply_ry_bit<8>(st, 0.5f * p[0]);
            apply_ry_bit<4>(st, 0.5f * p[1]);
            apply_ry_bit<2>(st, 0.5f * p[2]);
            apply_ry_bit<1>(st, 0.5f * p[3]);
            apply_cnot<8, 4>(st);
            apply_cnot<4, 2>(st);
            apply_cnot<2, 1>(st);
            apply_cnot<1, 8>(st);
        }
#pragma unroll
        for (int i = 0; i < 16; i++) base[tid * 16 + i] = st[i];
    }
}

// ---------------- quantum: Z from 16 zpart partials, normalize attnT, circuit ----------------
__global__ __launch_bounds__(256) void quantum_kernel(
    const float* __restrict__ atn, const float* __restrict__ zp,
    const float* __restrict__ base, __half* __restrict__ zc192)
{
    int idx = blockIdx.x * 256 + threadIdx.x;
    if (idx >= NTOT_) return;
    int h  = idx >> 13;
    int bt = idx & (M_ - 1);

    const float4* zpp = (const float4*)(zp + (size_t)bt * 16);
    float4 a = zpp[0], b = zpp[1], c = zpp[2], d = zpp[3];
    float Z = (((a.x + a.y) + (a.z + a.w)) + ((b.x + b.y) + (b.z + b.w)))
            + (((c.x + c.y) + (c.z + c.w)) + ((d.x + d.y) + (d.z + d.w)));
    const float rz = 0.5f / Z;

    float ang[4];
#pragma unroll
    for (int q = 0; q < 4; q++)
        ang[q] = atn[(size_t)(h * 4 + q) * M_ + bt] * rz;

    float st[16];
#pragma unroll
    for (int i = 0; i < 16; i++) st[i] = base[h * 16 + i];

    apply_ry_bit<8>(st, ang[0]);
    apply_ry_bit<4>(st, ang[1]);
    apply_ry_bit<2>(st, ang[2]);
    apply_ry_bit<1>(st, ang[3]);

    float z[4] = {0.f, 0.f, 0.f, 0.f};
#pragma unroll
    for (int i = 0; i < 16; i++) {
        float p = st[i] * st[i];
        z[0] += (i & 8) ? -p : p;
        z[1] += (i & 4) ? -p : p;
        z[2] += (i & 2) ? -p : p;
        z[3] += (i & 1) ? -p : p;
    }

    __half hq[4], lq[4];
#pragma unroll
    for (int q = 0; q < 4; q++) {
        hq[q] = __float2half(z[q]);
        lq[q] = __float2half(z[q] - __half2float(hq[q]));
    }
    __half2 h01 = __halves2half2(hq[0], hq[1]);
    __half2 h23 = __halves2half2(hq[2], hq[3]);
    __half2 l01 = __halves2half2(lq[0], lq[1]);
    __half2 l23 = __halves2half2(lq[2], lq[3]);

    size_t o = (size_t)bt * 192 + h * 4;
    *(__half2*)(zc192 + o)       = h01;
    *(__half2*)(zc192 + o + 2)   = h23;
    *(__half2*)(zc192 + o + 64)  = l01;
    *(__half2*)(zc192 + o + 66)  = l23;
    *(__half2*)(zc192 + o + 128) = h01;
    *(__half2*)(zc192 + o + 130) = h23;
}

// ---------------- launch ----------------
extern "C" void kernel_launch(void* const* d_in, const int* in_sizes, int n_in,
                              void* d_out, int out_size)
{
    (void)in_sizes; (void)n_in; (void)out_size;
    const float* x  = (const float*)d_in[0];
    const float* Wq = (const float*)d_in[1];
    const float* Wk = (const float*)d_in[2];
    const float* Wv = (const float*)d_in[3];
    const float* Wo = (const float*)d_in[4];
    const float* qp = (const float*)d_in[5];
    float* out = (float*)d_out;

    __half *xh, *wqT, *wkT, *gt, *yh, *wvs, *vts, *zc192, *wo192;
    float *zp, *atn, *pb;
    cudaGetSymbolAddress((void**)&xh,    g_xh);
    cudaGetSymbolAddress((void**)&wqT,   g_wqT);
    cudaGetSymbolAddress((void**)&wkT,   g_wkT);
    cudaGetSymbolAddress((void**)&gt,    g_gt);
    cudaGetSymbolAddress((void**)&yh,    g_yh);
    cudaGetSymbolAddress((void**)&wvs,   g_wvsub);
    cudaGetSymbolAddress((void**)&vts,   g_vts);
    cudaGetSymbolAddress((void**)&zp,    g_zpart);
    cudaGetSymbolAddress((void**)&atn,   g_attnT);
    cudaGetSymbolAddress((void**)&zc192, g_zc192);
    cudaGetSymbolAddress((void**)&wo192, g_wo192);
    cudaGetSymbolAddress((void**)&pb,    g_base);

    cudaFuncSetAttribute((const void*)gemm_h<128, false>, cudaFuncAttributeMaxDynamicSharedMemorySize, SMEM_DYN_128);
    cudaFuncSetAttribute((const void*)gemm_h<128, true>,  cudaFuncAttributeMaxDynamicSharedMemorySize, SMEM_DYN_128);
    cudaFuncSetAttribute((const void*)gemm_h<64, false>,  cudaFuncAttributeMaxDynamicSharedMemorySize, SMEM_DYN_64);

    // fused prep + zero the atomic accumulator
    prep_kernel<<<9025, 256>>>(x, Wq, Wk, Wv, Wo, qp, xh, wqT, wkT, wvs, wo192, pb);
    cudaMemsetAsync(atn, 0, (size_t)64 * M_ * sizeof(float));

    // Gt = (Wq^T Wk / 32)^T (fp16 out)
    {
        dim3 g(E_ / 128, E_ / 64);
        gemm_h<64, false><<<g, 256, SMEM_DYN_64>>>(wkT, wqT, nullptr, gt, nullptr, nullptr,
                                                   E_, E_, E_, E_, 0, 0, 0, 1.f / 32.f);
    }
    // Vtsub = Wvsub @ x^T : single pass, fp16 direct (no split-K, no vred)
    {
        dim3 g(M_ / 128, 1);
        gemm_h<64, false><<<g, 256, SMEM_DYN_64>>>(wvs, xh, nullptr, vts, nullptr, nullptr,
                                                   E_, E_, E_, M_, 0, 0, 0, 1.f);
    }
    // Y = x @ G~ (fp16 out)
    {
        dim3 g(E_ / 128, M_ / 128);
        gemm_h<128, false><<<g, 256, SMEM_DYN_128>>>(xh, gt, nullptr, yh, nullptr, nullptr,
                                                     E_, E_, E_, E_, 0, 0, 0, 1.f);
    }
    // scores: exp(Y x^T - 4) fused with rowsums (zpart) and attnT accumulation (atomic)
    {
        dim3 g(T_ / 128, T_ / 128, B_);
        gemm_h<128, true><<<g, 256, SMEM_DYN_128>>>(yh, xh, zp, nullptr, vts, atn,
                                                    E_, E_, E_, T_,
                                                    (size_t)T_ * E_, (size_t)T_ * E_, (size_t)T_ * T_,
                                                    1.f);
    }
    quantum_kernel<<<NTOT_ / 256, 256>>>(atn, zp, pb, zc192);
    // out = zc @ WoSub^T via plane-concat K=192 fp16 GEMM
    {
        dim3 g(E_ / 128, M_ / 128);
        gemm_h<128, false><<<g, 256, SMEM_DYN_128>>>(zc192, wo192, out, nullptr, nullptr, nullptr,
                                                     192, 192, 192, E_, 0, 0, 0, 1.f);
    }
}

// round 17
// speedup vs baseline: 1.0130x; 1.0064x over previous
#include <cuda_runtime.h>
#include <cuda_fp16.h>
#include <math.h>
#include <stdint.h>

// ---------------- problem constants ----------------
constexpr int B_  = 4;
constexpr int T_  = 2048;
constexpr int E_  = 1024;
constexpr int H_  = 16;
constexpr int LQ_ = 2;
constexpr int M_  = B_ * T_;             // 8192
constexpr int NTOT_ = M_ * H_;           // 131072

// ---------------- scratch (device globals; no allocs allowed) ----------------
__device__ __half g_xh[(size_t)M_ * E_];
__device__ __half g_wqT[(size_t)E_ * E_];          // Wq^T (fp16)
__device__ __half g_wkT[(size_t)E_ * E_];          // Wk^T (fp16)
__device__ __half g_gt[(size_t)E_ * E_];           // G~^T = (Wq^T Wk / 32)^T (fp16)
__device__ __half g_yh[(size_t)M_ * E_];           // Y = x G~ (fp16)
__device__ __half g_wvsub[(size_t)64 * E_];        // gathered 64 rows of Wv (fp16)
__device__ __half g_vts[(size_t)64 * M_];          // Vtsub [64][M] (fp16)
__device__ float  g_zpart[(size_t)M_ * 16];        // per-(row, s-tile) exp partial sums
__device__ float  g_attnT[(size_t)64 * M_];        // attn~^T accumulated via atomics
__device__ __half g_zc192[(size_t)M_ * 192];       // [z_hi | z_lo | z_hi]
__device__ __half g_wo192[(size_t)E_ * 192];       // [W_hi | W_hi | W_lo]
__device__ float  g_base[H_ * 16];

// ---------------- helpers ----------------
__device__ __forceinline__ uint32_t smem_u32(const void* p) {
    uint32_t a;
    asm("{ .reg .u64 t; cvta.to.shared.u64 t, %1; cvt.u32.u64 %0, t; }" : "=r"(a) : "l"(p));
    return a;
}
#define CP16(dst, src) asm volatile("cp.async.cg.shared.global [%0], [%1], 16;" :: "r"(dst), "l"(src))
#define CPCOMMIT()     asm volatile("cp.async.commit_group;")
#define CPWAIT2()      asm volatile("cp.async.wait_group 2;")
#define CPWAIT0()      asm volatile("cp.async.wait_group 0;")

__device__ __forceinline__ void ldmx4(uint32_t* r, uint32_t addr) {
    asm volatile("ldmatrix.sync.aligned.m8n8.x4.shared.b16 {%0,%1,%2,%3}, [%4];"
                 : "=r"(r[0]), "=r"(r[1]), "=r"(r[2]), "=r"(r[3]) : "r"(addr));
}
__device__ __forceinline__ void mma16816(float* c, const uint32_t* a, const uint32_t* b) {
    asm volatile(
        "mma.sync.aligned.m16n8k16.row.col.f32.f16.f16.f32 "
        "{%0,%1,%2,%3}, {%4,%5,%6,%7}, {%8,%9}, {%0,%1,%2,%3};"
        : "+f"(c[0]), "+f"(c[1]), "+f"(c[2]), "+f"(c[3])
        : "r"(a[0]), "r"(a[1]), "r"(a[2]), "r"(a[3]), "r"(b[0]), "r"(b[1]));
}
__device__ __forceinline__ uint32_t pack_f16(float lo, float hi) {
    uint32_t u;
    asm("cvt.rn.f16x2.f32 %0, %1, %2;" : "=r"(u) : "f"(hi), "f"(lo));
    return u;
}

// FMA-pipe exp(s - 4): magic-number range reduction + degree-5 2^f poly.
__device__ __forceinline__ float fexp4(float s) {
    float y = fmaf(s, 1.44269504f, -5.77078016f);      // (s-4)*log2(e)
    y = fminf(fmaxf(y, -30.f), 15.f);
    float t = y + 12582912.f;                           // 1.5*2^23 magic
    int   n = __float_as_int(t) - 0x4B400000;
    float f = y - (t - 12582912.f);
    float p =          1.3333558e-3f;
    p = fmaf(p, f, 9.6181291e-3f);
    p = fmaf(p, f, 5.5504109e-2f);
    p = fmaf(p, f, 2.4022651e-1f);
    p = fmaf(p, f, 6.9314718e-1f);
    p = fmaf(p, f, 1.0f);
    return __int_as_float(__float_as_int(p) + (n << 23));
}

// ---------------- fp16 single-pass NT GEMM (mma.sync), BM x 128 tiles, BK=32 ----------------
// C[m,n] = alpha * sum_k A[m,k]*B[n,k]; fp32 acc. K%32==0.
// EXPM: fused softmax-numerator + attn epilogue (exp tile, rowsums, Vt x expT -> atomics).
// DUAL: grid(64,17); y<16 runs primary params (x<8, others exit); y==16 runs the
//       secondary (A2,B2,Ch2,ldc2,alpha2) job across all 64 x-blocks with row0=0.
constexpr int LDSB  = 80;                  // padded row: 32 halves (64B) + 16B pad

template <int BM, bool EXPM, bool DUAL>
__global__ __launch_bounds__(256, 2) void gemm_h(
    const __half* __restrict__ Ah, const __half* __restrict__ Bh,
    float* __restrict__ Cf, __half* __restrict__ Ch,
    const __half* __restrict__ Vt, float* __restrict__ Atn,
    const __half* __restrict__ A2, const __half* __restrict__ B2,
    __half* __restrict__ Ch2, int ldc2, float alpha2,
    int K, int lda, int ldb, int ldc,
    size_t sA, size_t sB, size_t sC, float alpha)
{
    constexpr int APLANE = BM * LDSB;
    constexpr int BPLANE = 128 * LDSB;
    constexpr int STAGE  = APLANE + BPLANE;
    constexpr int NSTG   = 4;
    constexpr int MF     = BM / 32;

    extern __shared__ char smem[];
    const uint32_t sb = smem_u32(smem);
    const int tid = threadIdx.x;
    const int lane = tid & 31;
    const int warp = tid >> 5;

    int by = blockIdx.y;
    const int bx = blockIdx.x;
    if constexpr (DUAL) {
        if (by < 16) {
            if (bx >= 8) return;                 // Gt region: only x<8
        } else {
            Ah = A2; Bh = B2; Ch = Ch2;          // secondary job (Vtsub)
            ldc = ldc2; alpha = alpha2;
            by = 0;
        }
    }
    const int row0 = by * BM;
    const int col0 = bx * 128;
    const int zb = blockIdx.z;

    Ah += zb * sA;
    Bh += zb * sB;

    // A loader mapping
    const __half* gA;
    uint32_t aoff;
    if constexpr (BM == 128) {
        const int ar = tid >> 1, ac = (tid & 1) * 2;
        gA = Ah + (size_t)(row0 + ar) * lda + ac * 8;
        aoff = (uint32_t)(ar * LDSB + ac * 16);
    } else {
        const int ar = tid >> 2, ac = tid & 3;
        gA = Ah + (size_t)(row0 + ar) * lda + ac * 8;
        aoff = (uint32_t)(ar * LDSB + ac * 16);
    }
    // B loader mapping (128 rows, 2 chunks/thread)
    const int br = tid >> 1, bc = (tid & 1) * 2;
    const __half* gB = Bh + (size_t)(col0 + br) * ldb + bc * 8;
    const uint32_t boff = (uint32_t)(APLANE + br * LDSB + bc * 16);

    const int ntiles = K >> 5;

    auto load_tile = [&](int kt, int slot) {
        const uint32_t base = sb + (uint32_t)slot * STAGE;
        const __half* sa = gA + (size_t)kt * 32;
        const __half* sbp = gB + (size_t)kt * 32;
        if constexpr (BM == 128) {
            CP16(base + aoff,      sa);
            CP16(base + aoff + 16, sa + 8);
        } else {
            CP16(base + aoff, sa);
        }
        CP16(base + boff,      sbp);
        CP16(base + boff + 16, sbp + 8);
    };

    load_tile(0, 0); CPCOMMIT();
    load_tile(1, 1); CPCOMMIT();
    load_tile(2, 2); CPCOMMIT();

    const int wm = (warp & 1) * (BM / 2);
    const int wn = (warp >> 1) * 32;

    float acc[MF][4][4];
#pragma unroll
    for (int i = 0; i < MF; i++)
#pragma unroll
        for (int j = 0; j < 4; j++)
#pragma unroll
            for (int r = 0; r < 4; r++) acc[i][j][r] = 0.f;

    const uint32_t a_off = (uint32_t)((wm + (lane & 15)) * LDSB + ((lane >> 4) * 8) * 2);
    const int nrow = (lane & 7) + ((lane >> 4) * 8);
    const uint32_t b_off = (uint32_t)(APLANE + (wn + nrow) * LDSB + (((lane >> 3) & 1) * 8) * 2);

    for (int i = 0; i < ntiles; i++) {
        CPWAIT2();
        __syncthreads();
        if (i + 3 < ntiles) load_tile(i + 3, (i + 3) % NSTG);
        CPCOMMIT();

        const uint32_t st = sb + (uint32_t)(i % NSTG) * STAGE;
#pragma unroll
        for (int kk = 0; kk < 2; kk++) {
            uint32_t ah[MF][4], bh[4][2];
#pragma unroll
            for (int im = 0; im < MF; im++)
                ldmx4(ah[im], st + a_off + (uint32_t)(im * 16 * LDSB + kk * 32));
#pragma unroll
            for (int jb = 0; jb < 2; jb++) {
                uint32_t r[4];
                ldmx4(r, st + b_off + (uint32_t)(jb * 16 * LDSB + kk * 32));
                bh[jb * 2][0] = r[0];     bh[jb * 2][1] = r[1];
                bh[jb * 2 + 1][0] = r[2]; bh[jb * 2 + 1][1] = r[3];
            }
#pragma unroll
            for (int im = 0; im < MF; im++)
#pragma unroll
                for (int jn = 0; jn < 4; jn++)
                    mma16816(acc[im][jn], ah[im], bh[jn]);
        }
        __syncthreads();
    }

    if constexpr (EXPM) {
        // ---------- fused exp + rowsum + attnT epilogue (BM == 128) ----------
        constexpr uint32_t SROW = 272;                  // 128 halves + 8-half pad (17x16B)
        const uint32_t s16o  = sb;                      // exp fp16 tile [128 q][SROW]
        const uint32_t vt16o = sb + 128u * SROW;        // Vt fp16 tile [64 v][SROW]

        // issue Vt slice load: rows v=0..63, cols s = zb*T_ + col0 .. +128
        {
            const __half* vsrc = Vt + (size_t)(tid >> 2) * M_ + (size_t)zb * T_ + col0 + (tid & 3) * 32;
            const uint32_t vdst = vt16o + (uint32_t)((tid >> 2) * SROW + (tid & 3) * 64);
            CP16(vdst,      vsrc);
            CP16(vdst + 16, vsrc + 8);
            CP16(vdst + 32, vsrc + 16);
            CP16(vdst + 48, vsrc + 24);
            CPCOMMIT();
        }
        // exp in registers -> fp16 smem tile
        const int er = wm + (lane >> 2);
        const int ec = wn + (lane & 3) * 2;
#pragma unroll
        for (int im = 0; im < 4; im++)
#pragma unroll
            for (int jn = 0; jn < 4; jn++) {
                float e0 = fexp4(acc[im][jn][0]);
                float e1 = fexp4(acc[im][jn][1]);
                float e2 = fexp4(acc[im][jn][2]);
                float e3 = fexp4(acc[im][jn][3]);
                uint32_t adr = s16o + (uint32_t)((er + im * 16) * SROW + (ec + jn * 8) * 2);
                uint32_t p01 = pack_f16(e0, e1);
                uint32_t p23 = pack_f16(e2, e3);
                asm volatile("st.shared.b32 [%0], %1;" :: "r"(adr),            "r"(p01));
                asm volatile("st.shared.b32 [%0], %1;" :: "r"(adr + 8 * SROW), "r"(p23));
            }
        CPWAIT0();
        __syncthreads();

        // row sums -> zpart (Cf)
        {
            const int r2 = tid >> 1;
            const uint32_t rb = s16o + (uint32_t)(r2 * SROW + (tid & 1) * 128);
            float rs = 0.f;
#pragma unroll
            for (int j = 0; j < 8; j++) {
                uint32_t u0, u1, u2, u3;
                asm volatile("ld.shared.v4.b32 {%0,%1,%2,%3}, [%4];"
                             : "=r"(u0), "=r"(u1), "=r"(u2), "=r"(u3) : "r"(rb + j * 16));
                float2 a = __half22float2(*(__half2*)&u0);
                float2 b = __half22float2(*(__half2*)&u1);
                float2 c = __half22float2(*(__half2*)&u2);
                float2 d = __half22float2(*(__half2*)&u3);
                rs += (a.x + a.y) + (b.x + b.y) + (c.x + c.y) + (d.x + d.y);
            }
            rs += __shfl_xor_sync(0xFFFFFFFFu, rs, 1);
            if ((tid & 1) == 0)
                Cf[(size_t)(zb * T_ + row0 + r2) * 16 + blockIdx.x] = rs;
        }

        // attnT: C2[64 v][16 q per warp] = Vt_slice x expTile^T via mma, atomicAdd out
        {
            const int qw = warp * 16;
            const uint32_t a2 = vt16o + (uint32_t)((lane & 15) * SROW + ((lane >> 4) * 8) * 2);
            const int nrow2 = (lane & 7) + ((lane >> 4) * 8);
            const uint32_t b2 = s16o + (uint32_t)((qw + nrow2) * SROW + (((lane >> 3) & 1) * 8) * 2);
            float c2[4][2][4];
#pragma unroll
            for (int i2 = 0; i2 < 4; i2++)
#pragma unroll
                for (int j2 = 0; j2 < 2; j2++)
#pragma unroll
                    for (int r2 = 0; r2 < 4; r2++) c2[i2][j2][r2] = 0.f;
#pragma unroll
            for (int k2 = 0; k2 < 8; k2++) {
                uint32_t bf[4];
                ldmx4(bf, b2 + (uint32_t)(k2 * 32));
#pragma unroll
                for (int im2 = 0; im2 < 4; im2++) {
                    uint32_t af[4];
                    ldmx4(af, a2 + (uint32_t)(im2 * 16 * SROW + k2 * 32));
                    mma16816(c2[im2][0], af, bf);
                    mma16816(c2[im2][1], af, bf + 2);
                }
            }
            const int vb = lane >> 2;
            const int q0 = row0 + qw + (lane & 3) * 2;
            const size_t cb = (size_t)zb * T_;
#pragma unroll
            for (int im2 = 0; im2 < 4; im2++)
#pragma unroll
                for (int jn2 = 0; jn2 < 2; jn2++) {
                    const int v = im2 * 16 + vb;
                    const size_t q = cb + q0 + jn2 * 8;
                    atomicAdd(Atn + (size_t)v * M_ + q,           c2[im2][jn2][0]);
                    atomicAdd(Atn + (size_t)v * M_ + q + 1,       c2[im2][jn2][1]);
                    atomicAdd(Atn + (size_t)(v + 8) * M_ + q,     c2[im2][jn2][2]);
                    atomicAdd(Atn + (size_t)(v + 8) * M_ + q + 1, c2[im2][jn2][3]);
                }
        }
        return;
    }

    // ---- standard epilogue: frags -> smem fp32 -> global ----
    float* se = (float*)smem;                        // [BM][132]
    const int er = wm + (lane >> 2);
    const int ec = wn + (lane & 3) * 2;
#pragma unroll
    for (int im = 0; im < MF; im++)
#pragma unroll
        for (int jn = 0; jn < 4; jn++) {
            float* p0 = se + (size_t)(er + im * 16) * 132 + ec + jn * 8;
            p0[0] = acc[im][jn][0];
            p0[1] = acc[im][jn][1];
            p0[132 * 8]     = acc[im][jn][2];
            p0[132 * 8 + 1] = acc[im][jn][3];
        }
    __syncthreads();
    {
        constexpr int TPR = 256 / BM;
        constexpr int CW  = 128 / TPR;
        const int row = tid / TPR;
        const int hc  = (tid % TPR) * CW;
        const size_t crow = (size_t)zb * sC + (size_t)(row0 + row) * ldc + col0 + hc;
#pragma unroll
        for (int j = 0; j < CW / 4; j++) {
            float4 v = *(const float4*)(se + (size_t)row * 132 + hc + j * 4);
            v.x *= alpha; v.y *= alpha; v.z *= alpha; v.w *= alpha;
            if (Cf) *(float4*)(Cf + crow + j * 4) = v;
            if (Ch) {
                uint2 u = make_uint2(pack_f16(v.x, v.y), pack_f16(v.z, v.w));
                *(uint2*)(Ch + crow + j * 4) = u;
            }
        }
    }
}

constexpr int SMEM_DYN_128 = 4 * (128 + 128) * LDSB;   // 81920
constexpr int SMEM_DYN_64  = 4 * (64 + 128) * LDSB;    // 61440

// ---------------- quantum circuit device pieces ----------------
template <int BIT>
__device__ __forceinline__ void apply_ry_bit(float st[16], float half_theta)
{
    float s, c;
    sincosf(half_theta, &s, &c);
#pragma unroll
    for (int i = 0; i < 16; i++) {
        if (!(i & BIT)) {
            float a0 = st[i], a1 = st[i | BIT];
            st[i]       = c * a0 - s * a1;
            st[i | BIT] = s * a0 + c * a1;
        }
    }
}
template <int BC, int BT>
__device__ __forceinline__ void apply_cnot(float st[16])
{
#pragma unroll
    for (int i = 0; i < 16; i++) {
        if ((i & BC) && !(i & BT)) {
            float tmp = st[i]; st[i] = st[i | BT]; st[i | BT] = tmp;
        }
    }
}

// ---------------- fused prep: conv x, transpose Wq/Wk, wvsub, wosub, zero attnT, base ----------------
__global__ __launch_bounds__(256) void prep_kernel(
    const float* __restrict__ x,  const float* __restrict__ Wq,
    const float* __restrict__ Wk, const float* __restrict__ Wv,
    const float* __restrict__ Wo, const float* __restrict__ qp,
    __half* __restrict__ xh, __half* __restrict__ wqT, __half* __restrict__ wkT,
    __half* __restrict__ wvs, __half* __restrict__ wo192, float* __restrict__ base,
    float* __restrict__ atn)
{
    __shared__ float ts[64][65];
    const int b = blockIdx.x;
    const int tid = threadIdx.x;

    if (b < 8192) {
        size_t i = ((size_t)b * 256 + tid) * 4;
        float4 v = *(const float4*)(x + i);
        *(uint2*)(xh + i) = make_uint2(pack_f16(v.x, v.y), pack_f16(v.z, v.w));
    } else if (b < 8704) {
        const bool isQ = b < 8448;
        const int tile = b - (isQ ? 8192 : 8448);
        const float* W = isQ ? Wq : Wk;
        __half* WT = isQ ? wqT : wkT;
        const int tr = (tile >> 4) * 64;
        const int tc = (tile & 15) * 64;
        const int lr = tid >> 2;
        const int lc = (tid & 3) * 16;
#pragma unroll
        for (int j = 0; j < 16; j += 4) {
            float4 v = *(const float4*)(W + (size_t)(tr + lr) * E_ + tc + lc + j);
            ts[lr][lc + j + 0] = v.x; ts[lr][lc + j + 1] = v.y;
            ts[lr][lc + j + 2] = v.z; ts[lr][lc + j + 3] = v.w;
        }
        __syncthreads();
#pragma unroll
        for (int j = 0; j < 16; j += 4) {
            uint2 u = make_uint2(
                pack_f16(ts[lc + j + 0][lr], ts[lc + j + 1][lr]),
                pack_f16(ts[lc + j + 2][lr], ts[lc + j + 3][lr]));
            *(uint2*)(WT + (size_t)(tc + lr) * E_ + tr + lc + j) = u;
        }
    } else if (b < 8768) {
        int idx = (b - 8704) * 256 + tid;
        int j = idx >> 8;
        int c = (idx & 255) * 4;
        const float* src = Wv + (size_t)((j >> 2) * 64 + (j & 3)) * E_ + c;
        float4 v = *(const float4*)src;
        *(uint2*)(wvs + (size_t)j * E_ + c) = make_uint2(pack_f16(v.x, v.y), pack_f16(v.z, v.w));
    } else if (b < 9024) {
        int idx = (b - 8768) * 256 + tid;
        int e = idx >> 6, j = idx & 63;
        float v = Wo[(size_t)e * E_ + ((j >> 2) << 6) + (j & 3)];
        __half h = __float2half(v);
        __half l = __float2half(v - __half2float(h));
        size_t o = (size_t)e * 192 + j;
        wo192[o]       = h;
        wo192[o + 64]  = h;
        wo192[o + 128] = l;
    } else if (b < 9536) {
        // zero attnT: 64*8192 floats = 512 blocks x 256 thr x float4
        size_t i = ((size_t)(b - 9024) * 256 + tid) * 4;
        *(float4*)(atn + i) = make_float4(0.f, 0.f, 0.f, 0.f);
    } else if (tid < H_) {
        float st[16];
#pragma unroll
        for (int i = 0; i < 16; i++) st[i] = 0.f;
        st[0] = 1.f;
#pragma unroll
        for (int l = 0; l < LQ_; l++) {
            const float* p = qp + (tid * LQ_ + l) * 4;
            apply_ry_bit<8>(st, 0.5f * p[0]);
            apply_ry_bit<4>(st, 0.5f * p[1]);
            apply_ry_bit<2>(st, 0.5f * p[2]);
            apply_ry_bit<1>(st, 0.5f * p[3]);
            apply_cnot<8, 4>(st);
            apply_cnot<4, 2>(st);
            apply_cnot<2, 1>(st);
            apply_cnot<1, 8>(st);
        }
#pragma unroll
        for (int i = 0; i < 16; i++) base[tid * 16 + i] = st[i];
    }
}

// ---------------- quantum: Z from 16 zpart partials, normalize attnT, circuit ----------------
__global__ __launch_bounds__(256) void quantum_kernel(
    const float* __restrict__ atn, const float* __restrict__ zp,
    const float* __restrict__ base, __half* __restrict__ zc192)
{
    int idx = blockIdx.x * 256 + threadIdx.x;
    if (idx >= NTOT_) return;
    int h  = idx >> 13;
    int bt = idx & (M_ - 1);

    const float4* zpp = (const float4*)(zp + (size_t)bt * 16);
    float4 a = zpp[0], b = zpp[1], c = zpp[2], d = zpp[3];
    float Z = (((a.x + a.y) + (a.z + a.w)) + ((b.x + b.y) + (b.z + b.w)))
            + (((c.x + c.y) + (c.z + c.w)) + ((d.x + d.y) + (d.z + d.w)));
    const float rz = 0.5f / Z;

    float ang[4];
#pragma unroll
    for (int q = 0; q < 4; q++)
        ang[q] = atn[(size_t)(h * 4 + q) * M_ + bt] * rz;

    float st[16];
#pragma unroll
    for (int i = 0; i < 16; i++) st[i] = base[h * 16 + i];

    apply_ry_bit<8>(st, ang[0]);
    apply_ry_bit<4>(st, ang[1]);
    apply_ry_bit<2>(st, ang[2]);
    apply_ry_bit<1>(st, ang[3]);

    float z[4] = {0.f, 0.f, 0.f, 0.f};
#pragma unroll
    for (int i = 0; i < 16; i++) {
        float p = st[i] * st[i];
        z[0] += (i & 8) ? -p : p;
        z[1] += (i & 4) ? -p : p;
        z[2] += (i & 2) ? -p : p;
        z[3] += (i & 1) ? -p : p;
    }

    __half hq[4], lq[4];
#pragma unroll
    for (int q = 0; q < 4; q++) {
        hq[q] = __float2half(z[q]);
        lq[q] = __float2half(z[q] - __half2float(hq[q]));
    }
    __half2 h01 = __halves2half2(hq[0], hq[1]);
    __half2 h23 = __halves2half2(hq[2], hq[3]);
    __half2 l01 = __halves2half2(lq[0], lq[1]);
    __half2 l23 = __halves2half2(lq[2], lq[3]);

    size_t o = (size_t)bt * 192 + h * 4;
    *(__half2*)(zc192 + o)       = h01;
    *(__half2*)(zc192 + o + 2)   = h23;
    *(__half2*)(zc192 + o + 64)  = l01;
    *(__half2*)(zc192 + o + 66)  = l23;
    *(__half2*)(zc192 + o + 128) = h01;
    *(__half2*)(zc192 + o + 130) = h23;
}

// ---------------- launch ----------------
extern "C" void kernel_launch(void* const* d_in, const int* in_sizes, int n_in,
                              void* d_out, int out_size)
{
    (void)in_sizes; (void)n_in; (void)out_size;
    const float* x  = (const float*)d_in[0];
    const float* Wq = (const float*)d_in[1];
    const float* Wk = (const float*)d_in[2];
    const float* Wv = (const float*)d_in[3];
    const float* Wo = (const float*)d_in[4];
    const float* qp = (const float*)d_in[5];
    float* out = (float*)d_out;

    __half *xh, *wqT, *wkT, *gt, *yh, *wvs, *vts, *zc192, *wo192;
    float *zp, *atn, *pb;
    cudaGetSymbolAddress((void**)&xh,    g_xh);
    cudaGetSymbolAddress((void**)&wqT,   g_wqT);
    cudaGetSymbolAddress((void**)&wkT,   g_wkT);
    cudaGetSymbolAddress((void**)&gt,    g_gt);
    cudaGetSymbolAddress((void**)&yh,    g_yh);
    cudaGetSymbolAddress((void**)&wvs,   g_wvsub);
    cudaGetSymbolAddress((void**)&vts,   g_vts);
    cudaGetSymbolAddress((void**)&zp,    g_zpart);
    cudaGetSymbolAddress((void**)&atn,   g_attnT);
    cudaGetSymbolAddress((void**)&zc192, g_zc192);
    cudaGetSymbolAddress((void**)&wo192, g_wo192);
    cudaGetSymbolAddress((void**)&pb,    g_base);

    cudaFuncSetAttribute((const void*)gemm_h<128, false, false>, cudaFuncAttributeMaxDynamicSharedMemorySize, SMEM_DYN_128);
    cudaFuncSetAttribute((const void*)gemm_h<128, true,  false>, cudaFuncAttributeMaxDynamicSharedMemorySize, SMEM_DYN_128);
    cudaFuncSetAttribute((const void*)gemm_h<64,  false, true>,  cudaFuncAttributeMaxDynamicSharedMemorySize, SMEM_DYN_64);

    // fused prep (includes attnT zeroing)
    prep_kernel<<<9537, 256>>>(x, Wq, Wk, Wv, Wo, qp, xh, wqT, wkT, wvs, wo192, pb, atn);

    // merged launch: Gt = (Wq^T Wk / 32)^T  (y<16, x<8)  +  Vtsub = Wvsub @ x^T (y==16)
    {
        dim3 g(64, 17);
        gemm_h<64, false, true><<<g, 256, SMEM_DYN_64>>>(
            wkT, wqT, nullptr, gt, nullptr, nullptr,
            wvs, xh, vts, M_, 1.f,
            E_, E_, E_, E_, 0, 0, 0, 1.f / 32.f);
    }
    // Y = x @ G~ (fp16 out)
    {
        dim3 g(E_ / 128, M_ / 128);
        gemm_h<128, false, false><<<g, 256, SMEM_DYN_128>>>(
            xh, gt, nullptr, yh, nullptr, nullptr,
            nullptr, nullptr, nullptr, 0, 0.f,
            E_, E_, E_, E_, 0, 0, 0, 1.f);
    }
    // scores: exp(Y x^T - 4) fused with rowsums (zpart) and attnT accumulation (atomic)
    {
        dim3 g(T_ / 128, T_ / 128, B_);
        gemm_h<128, true, false><<<g, 256, SMEM_DYN_128>>>(
            yh, xh, zp, nullptr, vts, atn,
            nullptr, nullptr, nullptr, 0, 0.f,
            E_, E_, E_, T_,
            (size_t)T_ * E_, (size_t)T_ * E_, (size_t)T_ * T_, 1.f);
    }
    quantum_kernel<<<NTOT_ / 256, 256>>>(atn, zp, pb, zc192);
    // out = zc @ WoSub^T via plane-concat K=192 fp16 GEMM
    {
        dim3 g(E_ / 128, M_ / 128);
        gemm_h<128, false, false><<<g, 256, SMEM_DYN_128>>>(
            zc192, wo192, out, nullptr, nullptr, nullptr,
            nullptr, nullptr, nullptr, 0, 0.f,
            192, 192, 192, E_, 0, 0, 0, 1.f);
    }
}